// round 16
// baseline (speedup 1.0000x reference)
#include <cuda_runtime.h>
#include <cuda_fp16.h>
#include <cstdint>

#define NN 200000
#define EE 200000

// ---------------- scratch (static device globals; no runtime allocation) ----------------
__device__ __half   g_h   [(size_t)NN * 256];
__device__ __half   g_hw0 [(size_t)NN * 256];
__device__ __half   g_hw1 [(size_t)NN * 256];
__device__ __half   g_acc0[(size_t)NN * 256];
__device__ __half   g_acc1[(size_t)NN * 256];
__device__ __half   g_xbu [(size_t)NN * 256];
__device__ __half   g_xtd [(size_t)NN * 256];
__device__ float    g_as0 [NN * 4];
__device__ float    g_as1 [NN * 4];
__device__ float    g_ad0 [NN * 4];
__device__ float    g_ad1 [NN * 4];
__device__ float    g_den0[NN * 4];
__device__ float    g_den1[NN * 4];
__device__ float    g_e0  [(size_t)EE * 4];
__device__ float    g_e1  [(size_t)EE * 4];
__device__ __half   g_wt  [4 * 65536];   // half-rounded Wp | W_bu | W_td | Wf

// ---------------- helpers ----------------
__device__ __forceinline__ unsigned pack_h2(float a, float b) {
    __half2 h = __floats2half2_rn(a, b);
    return *reinterpret_cast<unsigned*>(&h);
}

__device__ __forceinline__ void mma16(float c[4], const unsigned a[4], const unsigned b[2]) {
    asm volatile(
        "mma.sync.aligned.m16n8k16.row.col.f32.f16.f16.f32 "
        "{%0,%1,%2,%3}, {%4,%5,%6,%7}, {%8,%9}, {%0,%1,%2,%3};\n"
        : "+f"(c[0]), "+f"(c[1]), "+f"(c[2]), "+f"(c[3])
        : "r"(a[0]), "r"(a[1]), "r"(a[2]), "r"(a[3]), "r"(b[0]), "r"(b[1]));
}

__device__ __forceinline__ void ldsm4(unsigned& r0, unsigned& r1, unsigned& r2, unsigned& r3,
                                      uint32_t addr) {
    asm volatile("ldmatrix.sync.aligned.m8n8.x4.shared.b16 {%0,%1,%2,%3}, [%4];\n"
                 : "=r"(r0), "=r"(r1), "=r"(r2), "=r"(r3) : "r"(addr));
}
__device__ __forceinline__ void ldsm4t(unsigned& r0, unsigned& r1, unsigned& r2, unsigned& r3,
                                       uint32_t addr) {
    asm volatile("ldmatrix.sync.aligned.m8n8.x4.trans.shared.b16 {%0,%1,%2,%3}, [%4];\n"
                 : "=r"(r0), "=r"(r1), "=r"(r2), "=r"(r3) : "r"(addr));
}

__device__ __forceinline__ void cp16(void* smem_dst, const void* gsrc, bool pred) {
    uint32_t s = (uint32_t)__cvta_generic_to_shared(smem_dst);
    int sz = pred ? 16 : 0;
    asm volatile("cp.async.cg.shared.global [%0], [%1], 16, %2;\n"
                 :: "r"(s), "l"(gsrc), "r"(sz));
}
__device__ __forceinline__ void cp_commit() { asm volatile("cp.async.commit_group;\n"); }
template<int N>
__device__ __forceinline__ void cp_wait() { asm volatile("cp.async.wait_group %0;\n" :: "n"(N)); }

__device__ __forceinline__ void redh4(__half* p, unsigned h2a, unsigned h2b) {
    asm volatile("red.global.add.noftz.v2.f16x2 [%0], {%1,%2};\n"
                 :: "l"(p), "r"(h2a), "r"(h2b) : "memory");
}

__device__ __forceinline__ void red4(float* p, float4 v) {
    asm volatile("red.global.add.v4.f32 [%0], {%1,%2,%3,%4};\n"
                 :: "l"(p), "f"(v.x), "f"(v.y), "f"(v.z), "f"(v.w) : "memory");
}

__device__ __forceinline__ float leaky(float v) { return v > 0.f ? v : 0.2f * v; }

// smem geometry (halves)
#define AS_STRIDE 24
#define AS_STAGE_B (128u * AS_STRIDE * 2u)    // 6144
#define BSW_STRIDE 264                        // wide B: 256 cols + pad
#define BSW_STAGE_B (16u * BSW_STRIDE * 2u)   // 8448
#define BSN_STRIDE 136                        // narrow B: 128 cols + pad (final gemm)
#define BSN_STAGE_B (16u * BSN_STRIDE * 2u)   // 4352

// 512-thread wide compute: warp tile 32(m) x 64(n); 2 ldsm + 4 ldsm.t + 16 mma / k-tile
__device__ __forceinline__ void compute16w(uint32_t asBase, uint32_t bsBase, int s,
                                           float acc[2][8][4], int wm, int wn, int lane)
{
    int sel = lane >> 3, r = lane & 7;
    uint32_t arowoff = (uint32_t)((sel & 1) * 8 + r);
    uint32_t acol = (uint32_t)((sel >> 1) * 8);
    uint32_t kk = (uint32_t)((sel & 1) * 8 + r);
    unsigned a[2][4], b[8][2];
#pragma unroll
    for (int mt = 0; mt < 2; mt++) {
        uint32_t arow = (uint32_t)(wm * 32 + mt * 16) + arowoff;
        ldsm4(a[mt][0], a[mt][1], a[mt][2], a[mt][3],
              asBase + (uint32_t)s * AS_STAGE_B + arow * (AS_STRIDE * 2u) + acol * 2u);
    }
#pragma unroll
    for (int p = 0; p < 4; p++) {
        uint32_t ncol = (uint32_t)(wn * 64 + p * 16 + (sel >> 1) * 8);
        unsigned r0, r1, r2, r3;
        ldsm4t(r0, r1, r2, r3,
               bsBase + (uint32_t)s * BSW_STAGE_B + kk * (BSW_STRIDE * 2u) + ncol * 2u);
        b[p * 2][0] = r0;     b[p * 2][1] = r1;
        b[p * 2 + 1][0] = r2; b[p * 2 + 1][1] = r3;
    }
#pragma unroll
    for (int mt = 0; mt < 2; mt++)
#pragma unroll
        for (int nt = 0; nt < 8; nt++)
            mma16(acc[mt][nt], a[mt], b[nt]);
}

// 256-thread narrow compute (final GEMM), unchanged geometry
__device__ __forceinline__ void compute16n(uint32_t asBase, uint32_t bsBase, int s,
                                           float acc[4][4][4], int wm, int wn, int lane)
{
    int sel = lane >> 3, r = lane & 7;
    uint32_t arow0 = (uint32_t)((sel & 1) * 8 + r);
    uint32_t acol = (uint32_t)((sel >> 1) * 8);
    uint32_t kk = (uint32_t)((sel & 1) * 8 + r);
    unsigned a[4][4], b[4][2];
#pragma unroll
    for (int mt = 0; mt < 4; mt++) {
        uint32_t arow = (uint32_t)(wm * 64 + mt * 16) + arow0;
        ldsm4(a[mt][0], a[mt][1], a[mt][2], a[mt][3],
              asBase + (uint32_t)s * AS_STAGE_B + arow * (AS_STRIDE * 2u) + acol * 2u);
    }
#pragma unroll
    for (int p = 0; p < 2; p++) {
        uint32_t ncol = (uint32_t)(wn * 32 + p * 16 + (sel >> 1) * 8);
        unsigned r0, r1, r2, r3;
        ldsm4t(r0, r1, r2, r3,
               bsBase + (uint32_t)s * BSN_STAGE_B + kk * (BSN_STRIDE * 2u) + ncol * 2u);
        b[p * 2][0] = r0;     b[p * 2][1] = r1;
        b[p * 2 + 1][0] = r2; b[p * 2 + 1][1] = r3;
    }
#pragma unroll
    for (int mt = 0; mt < 4; mt++)
#pragma unroll
        for (int nt = 0; nt < 4; nt++)
            mma16(acc[mt][nt], a[mt], b[nt]);
}

// ---------------- GEMM1: 512 thr, BN=256, A fp32 reg-staged cvt, relu+bias, half out ----
__global__ void __launch_bounds__(512, 1) tgemm16_cvt_k(
    const float* __restrict__ A1,
    const __half* __restrict__ B, const float* __restrict__ bias,
    __half* __restrict__ C, int M, int K, int Nc)
{
    __shared__ __align__(16) __half As[3][128][AS_STRIDE];
    __shared__ __align__(16) __half Bs[3][16][BSW_STRIDE];

    int tid = threadIdx.x;
    int lane = tid & 31, wid = tid >> 5;
    int g = lane >> 2, t = lane & 3;
    int wm = wid & 3, wn = wid >> 2;
    int rowBase = blockIdx.x * 128;
    uint32_t asBase = (uint32_t)__cvta_generic_to_shared(&As[0][0][0]);
    uint32_t bsBase = (uint32_t)__cvta_generic_to_shared(&Bs[0][0][0]);

    float acc[2][8][4];
#pragma unroll
    for (int i = 0; i < 2; i++)
#pragma unroll
        for (int j = 0; j < 8; j++)
#pragma unroll
            for (int r = 0; r < 4; r++) acc[i][j][r] = 0.f;

    int ar = tid >> 1, ac = (tid & 1) * 8;   // A staging: tid < 256 only
    int br = tid >> 5, bc = (tid & 31) * 8;  // B: 16 rows x 32 chunks = all 512

    float4 pa0, pa1;
    const float4 z4 = make_float4(0.f, 0.f, 0.f, 0.f);

    auto aload = [&](int kt) {
        if (tid < 256) {
            int rr = rowBase + ar;
            pa0 = (rr < M) ? *reinterpret_cast<const float4*>(A1 + (size_t)rr * K + kt + ac) : z4;
            pa1 = (rr < M) ? *reinterpret_cast<const float4*>(A1 + (size_t)rr * K + kt + ac + 4) : z4;
        }
    };
    auto astore = [&](int sb) {
        if (tid < 256) {
            uint4 u;
            u.x = pack_h2(pa0.x, pa0.y); u.y = pack_h2(pa0.z, pa0.w);
            u.z = pack_h2(pa1.x, pa1.y); u.w = pack_h2(pa1.z, pa1.w);
            *reinterpret_cast<uint4*>(&As[sb][ar][ac]) = u;
        }
    };
    auto bload = [&](int kt, int sb) {
        cp16(&Bs[sb][br][bc], B + (size_t)(kt + br) * Nc + bc, true);
        cp_commit();
    };

    int ntiles = K / 16;
    aload(0); astore(0);
    aload(16);                 // tile 1 held in registers
    bload(0, 0); bload(16, 1);
    for (int kt = 0; kt < ntiles; kt++) {
        int s = kt % 3;
        cp_wait<1>();
        __syncthreads();
        if (kt + 1 < ntiles) astore((kt + 1) % 3);
        if (kt + 2 < ntiles) { aload((kt + 2) * 16); bload((kt + 2) * 16, (kt + 2) % 3); }
        else cp_commit();
        compute16w(asBase, bsBase, s, acc, wm, wn, lane);
    }

#pragma unroll
    for (int nt = 0; nt < 8; nt++) {
        int col = wn * 64 + nt * 8 + 2 * t;
        float2 bb = *reinterpret_cast<const float2*>(bias + col);
#pragma unroll
        for (int mt = 0; mt < 2; mt++) {
            int row0 = rowBase + wm * 32 + mt * 16 + g;
            int row1 = row0 + 8;
            float v00 = fmaxf(acc[mt][nt][0] + bb.x, 0.f);
            float v01 = fmaxf(acc[mt][nt][1] + bb.y, 0.f);
            float v10 = fmaxf(acc[mt][nt][2] + bb.x, 0.f);
            float v11 = fmaxf(acc[mt][nt][3] + bb.y, 0.f);
            if (row0 < M) *reinterpret_cast<unsigned*>(C + (size_t)row0 * Nc + col) = pack_h2(v00, v01);
            if (row1 < M) *reinterpret_cast<unsigned*>(C + (size_t)row1 * Nc + col) = pack_h2(v10, v11);
        }
    }
}

// ---------------- GEMM2: 512 thr, BN=256, fused attention-coeff + den epilogue ----------
__global__ void __launch_bounds__(512, 1) tgemm16_att_k(
    const __half* __restrict__ A1,
    const __half* __restrict__ B,
    __half* __restrict__ C, int M, int K, int Nc,
    const float* __restrict__ asrc, const float* __restrict__ adst,
    float* __restrict__ osrc, float* __restrict__ odst, float* __restrict__ oden)
{
    __shared__ __align__(16) __half As[3][128][AS_STRIDE];
    __shared__ __align__(16) __half Bs[3][16][BSW_STRIDE];
    __shared__ float attS[128][4];
    __shared__ float attD[128][4];

    int tid = threadIdx.x;
    int lane = tid & 31, wid = tid >> 5;
    int g = lane >> 2, t = lane & 3;
    int wm = wid & 3, wn = wid >> 2;     // wn == head
    int rowBase = blockIdx.x * 128;
    uint32_t asBase = (uint32_t)__cvta_generic_to_shared(&As[0][0][0]);
    uint32_t bsBase = (uint32_t)__cvta_generic_to_shared(&Bs[0][0][0]);

    reinterpret_cast<float*>(attS)[tid] = 0.f;
    reinterpret_cast<float*>(attD)[tid] = 0.f;

    float acc[2][8][4];
#pragma unroll
    for (int i = 0; i < 2; i++)
#pragma unroll
        for (int j = 0; j < 8; j++)
#pragma unroll
            for (int r = 0; r < 4; r++) acc[i][j][r] = 0.f;

    int ar = tid >> 1, ac = (tid & 1) * 8;
    int br = tid >> 5, bc = (tid & 31) * 8;

    auto loadtile = [&](int kt, int sb) {
        if (tid < 256) {
            int rr = rowBase + ar;
            cp16(&As[sb][ar][ac], A1 + (size_t)rr * K + kt + ac, rr < M);
        }
        cp16(&Bs[sb][br][bc], B + (size_t)(kt + br) * Nc + bc, true);
        cp_commit();
    };

    int ntiles = K / 16;
    loadtile(0, 0);
    loadtile(16, 1);
    for (int kt = 0; kt < ntiles; kt++) {
        int s = kt % 3;
        cp_wait<1>();
        __syncthreads();
        if (kt + 2 < ntiles) loadtile((kt + 2) * 16, (kt + 2) % 3);
        else cp_commit();
        compute16w(asBase, bsBase, s, acc, wm, wn, lane);
    }
    __syncthreads();

    float as_c[8][2], ad_c[8][2];
#pragma unroll
    for (int nt = 0; nt < 8; nt++) {
        int colG = wn * 64 + nt * 8 + 2 * t;
        float2 a2 = *reinterpret_cast<const float2*>(asrc + colG);
        float2 d2 = *reinterpret_cast<const float2*>(adst + colG);
        as_c[nt][0] = a2.x; as_c[nt][1] = a2.y;
        ad_c[nt][0] = d2.x; ad_c[nt][1] = d2.y;
    }

#pragma unroll
    for (int mt = 0; mt < 2; mt++) {
        float s0 = 0.f, d0 = 0.f, s1 = 0.f, d1 = 0.f;
#pragma unroll
        for (int nt = 0; nt < 8; nt++) {
            s0 += acc[mt][nt][0] * as_c[nt][0] + acc[mt][nt][1] * as_c[nt][1];
            d0 += acc[mt][nt][0] * ad_c[nt][0] + acc[mt][nt][1] * ad_c[nt][1];
            s1 += acc[mt][nt][2] * as_c[nt][0] + acc[mt][nt][3] * as_c[nt][1];
            d1 += acc[mt][nt][2] * ad_c[nt][0] + acc[mt][nt][3] * ad_c[nt][1];
        }
#pragma unroll
        for (int off = 1; off <= 2; off <<= 1) {
            s0 += __shfl_xor_sync(0xffffffffu, s0, off);
            d0 += __shfl_xor_sync(0xffffffffu, d0, off);
            s1 += __shfl_xor_sync(0xffffffffu, s1, off);
            d1 += __shfl_xor_sync(0xffffffffu, d1, off);
        }
        if (t == 0) {
            int lr = wm * 32 + mt * 16 + g;
            atomicAdd(&attS[lr][wn], s0);
            atomicAdd(&attD[lr][wn], d0);
            atomicAdd(&attS[lr + 8][wn], s1);
            atomicAdd(&attD[lr + 8][wn], d1);
        }
#pragma unroll
        for (int nt = 0; nt < 8; nt++) {
            int col = wn * 64 + nt * 8 + 2 * t;
            int row0 = rowBase + wm * 32 + mt * 16 + g;
            int row1 = row0 + 8;
            if (row0 < M) *reinterpret_cast<unsigned*>(C + (size_t)row0 * Nc + col)
                = pack_h2(acc[mt][nt][0], acc[mt][nt][1]);
            if (row1 < M) *reinterpret_cast<unsigned*>(C + (size_t)row1 * Nc + col)
                = pack_h2(acc[mt][nt][2], acc[mt][nt][3]);
        }
    }
    __syncthreads();
    {
        int lr = tid >> 2, h = tid & 3;
        int grow = rowBase + lr;
        if (grow < M) {
            float sv = attS[lr][h], dv = attD[lr][h];
            size_t o = (size_t)grow * 4 + h;
            osrc[o] = sv;
            odst[o] = dv;
            oden[o] = expf(leaky(sv + dv));   // self-loop softmax seed
        }
    }
}

// ---------------- final GEMM: 256 thr, concat(A1,A2)@Wf + bf, fused LN(128) + L2 --------
__global__ void __launch_bounds__(256) tgemm16_final_k(
    const __half* __restrict__ A1, const __half* __restrict__ A2, int K1,
    const __half* __restrict__ B, const float* __restrict__ bias,
    const float* __restrict__ gw, const float* __restrict__ bw,
    float* __restrict__ C, int M, int K)
{
    const int Nc = 128;
    __shared__ __align__(16) __half As[3][128][AS_STRIDE];
    __shared__ __align__(16) __half Bs[3][16][BSN_STRIDE];
    __shared__ float redS[128], redQ[128], redN[128];

    int tid = threadIdx.x;
    int lane = tid & 31, wid = tid >> 5;
    int g = lane >> 2, t = lane & 3;
    int wm = wid >> 2, wn = wid & 3;
    int rowBase = blockIdx.x * 128;
    uint32_t asBase = (uint32_t)__cvta_generic_to_shared(&As[0][0][0]);
    uint32_t bsBase = (uint32_t)__cvta_generic_to_shared(&Bs[0][0][0]);

    if (tid < 128) { redS[tid] = 0.f; redQ[tid] = 0.f; redN[tid] = 0.f; }

    float acc[4][4][4];
#pragma unroll
    for (int i = 0; i < 4; i++)
#pragma unroll
        for (int j = 0; j < 4; j++)
#pragma unroll
            for (int r = 0; r < 4; r++) acc[i][j][r] = 0.f;

    int ar = tid >> 1, ac = (tid & 1) * 8;
    int br = tid >> 4, bc = (tid & 15) * 8;

    auto loadtile = [&](int kt, int sb) {
        const __half* Ap; int kk, stride;
        if (kt < K1) { Ap = A1; kk = kt;      stride = K1;     }
        else         { Ap = A2; kk = kt - K1; stride = K - K1; }
        int rr = rowBase + ar;
        cp16(&As[sb][ar][ac], Ap + (size_t)rr * stride + kk + ac, rr < M);
        cp16(&Bs[sb][br][bc], B + (size_t)(kt + br) * Nc + bc, true);
        cp_commit();
    };

    int ntiles = K / 16;           // 32
    loadtile(0, 0);
    loadtile(16, 1);
    for (int kt = 0; kt < ntiles; kt++) {
        int s = kt % 3;
        cp_wait<1>();
        __syncthreads();
        if (kt + 2 < ntiles) loadtile((kt + 2) * 16, (kt + 2) % 3);
        else cp_commit();
        compute16n(asBase, bsBase, s, acc, wm, wn, lane);
    }
    __syncthreads();

#pragma unroll
    for (int nt = 0; nt < 4; nt++) {
        int col = wn * 32 + nt * 8 + 2 * t;
        float2 bb = *reinterpret_cast<const float2*>(bias + col);
#pragma unroll
        for (int mt = 0; mt < 4; mt++) {
            acc[mt][nt][0] += bb.x; acc[mt][nt][1] += bb.y;
            acc[mt][nt][2] += bb.x; acc[mt][nt][3] += bb.y;
        }
    }
#pragma unroll
    for (int mt = 0; mt < 4; mt++) {
        float s0 = 0.f, q0 = 0.f, s1 = 0.f, q1 = 0.f;
#pragma unroll
        for (int nt = 0; nt < 4; nt++) {
            s0 += acc[mt][nt][0] + acc[mt][nt][1];
            q0 += acc[mt][nt][0] * acc[mt][nt][0] + acc[mt][nt][1] * acc[mt][nt][1];
            s1 += acc[mt][nt][2] + acc[mt][nt][3];
            q1 += acc[mt][nt][2] * acc[mt][nt][2] + acc[mt][nt][3] * acc[mt][nt][3];
        }
#pragma unroll
        for (int off = 1; off <= 2; off <<= 1) {
            s0 += __shfl_xor_sync(0xffffffffu, s0, off);
            q0 += __shfl_xor_sync(0xffffffffu, q0, off);
            s1 += __shfl_xor_sync(0xffffffffu, s1, off);
            q1 += __shfl_xor_sync(0xffffffffu, q1, off);
        }
        if (t == 0) {
            int lr = wm * 64 + mt * 16 + g;
            atomicAdd(&redS[lr], s0); atomicAdd(&redQ[lr], q0);
            atomicAdd(&redS[lr + 8], s1); atomicAdd(&redQ[lr + 8], q1);
        }
    }
    __syncthreads();
#pragma unroll
    for (int mt = 0; mt < 4; mt++) {
        int lr0 = wm * 64 + mt * 16 + g, lr1 = lr0 + 8;
        float m0 = redS[lr0] * (1.f / 128.f), m1 = redS[lr1] * (1.f / 128.f);
        float var0 = redQ[lr0] * (1.f / 128.f) - m0 * m0;
        float var1 = redQ[lr1] * (1.f / 128.f) - m1 * m1;
        float r0 = rsqrtf(var0 + 1e-5f), r1 = rsqrtf(var1 + 1e-5f);
        float n0 = 0.f, n1 = 0.f;
#pragma unroll
        for (int nt = 0; nt < 4; nt++) {
            int col = wn * 32 + nt * 8 + 2 * t;
            float2 gg = *reinterpret_cast<const float2*>(gw + col);
            float2 b2 = *reinterpret_cast<const float2*>(bw + col);
            float y00 = (acc[mt][nt][0] - m0) * r0 * gg.x + b2.x;
            float y01 = (acc[mt][nt][1] - m0) * r0 * gg.y + b2.y;
            float y10 = (acc[mt][nt][2] - m1) * r1 * gg.x + b2.x;
            float y11 = (acc[mt][nt][3] - m1) * r1 * gg.y + b2.y;
            acc[mt][nt][0] = y00; acc[mt][nt][1] = y01;
            acc[mt][nt][2] = y10; acc[mt][nt][3] = y11;
            n0 += y00 * y00 + y01 * y01;
            n1 += y10 * y10 + y11 * y11;
        }
#pragma unroll
        for (int off = 1; off <= 2; off <<= 1) {
            n0 += __shfl_xor_sync(0xffffffffu, n0, off);
            n1 += __shfl_xor_sync(0xffffffffu, n1, off);
        }
        if (t == 0) { atomicAdd(&redN[lr0], n0); atomicAdd(&redN[lr1], n1); }
    }
    __syncthreads();
#pragma unroll
    for (int mt = 0; mt < 4; mt++) {
        int lr0 = wm * 64 + mt * 16 + g, lr1 = lr0 + 8;
        float inv0 = 1.f / fmaxf(sqrtf(redN[lr0]), 1e-12f);
        float inv1 = 1.f / fmaxf(sqrtf(redN[lr1]), 1e-12f);
        int row0 = rowBase + lr0, row1 = rowBase + lr1;
#pragma unroll
        for (int nt = 0; nt < 4; nt++) {
            int col = wn * 32 + nt * 8 + 2 * t;
            if (row0 < M) *reinterpret_cast<float2*>(C + (size_t)row0 * 128 + col)
                = make_float2(acc[mt][nt][0] * inv0, acc[mt][nt][1] * inv0);
            if (row1 < M) *reinterpret_cast<float2*>(C + (size_t)row1 * 128 + col)
                = make_float2(acc[mt][nt][2] * inv1, acc[mt][nt][3] * inv1);
        }
    }
}

// ---------------- convert weights once into g_wt (half) ----------------
__global__ void round_w_k(const float* __restrict__ wp, const float* __restrict__ w0,
                          const float* __restrict__ w1, const float* __restrict__ w2,
                          __half* __restrict__ out)
{
    int i = blockIdx.x * 256 + threadIdx.x;
    out[i]           = __float2half_rn(wp[i]);
    out[65536 + i]   = __float2half_rn(w0[i]);
    out[131072 + i]  = __float2half_rn(w1[i]);
    out[196608 + i]  = __float2half_rn(w2[i]);
}

// ---------------- fused edge pass: exp(logit) + segment-sum into den --------------------
__global__ void edge_expsum_k(const int* __restrict__ ei,
                              const float* __restrict__ asrc, const float* __restrict__ adst,
                              float* __restrict__ ebuf, float* __restrict__ den)
{
    int i = blockIdx.x * blockDim.x + threadIdx.x;
    if (i >= EE) return;
    int s = ei[i], d = ei[EE + i];
    float4 as = *reinterpret_cast<const float4*>(asrc + (size_t)s * 4);
    float4 ad = *reinterpret_cast<const float4*>(adst + (size_t)d * 4);
    float4 o;
    o.x = expf(leaky(as.x + ad.x));
    o.y = expf(leaky(as.y + ad.y));
    o.z = expf(leaky(as.z + ad.z));
    o.w = expf(leaky(as.w + ad.w));
    *reinterpret_cast<float4*>(ebuf + (size_t)i * 4) = o;
    red4(den + (size_t)d * 4, o);
}

// ---------------- edge scatter (half hw, half acc via v2.f16x2 reductions) --------------
__global__ void __launch_bounds__(256) edge_scatter_k(const int* __restrict__ ei,
        const float* __restrict__ ebuf, const float* __restrict__ den,
        const __half* __restrict__ hw, __half* __restrict__ acc)
{
    int idx = blockIdx.x * 4 + (threadIdx.x >> 6);
    int lane = threadIdx.x & 63;
    if (idx >= EE) return;
    int s = ei[idx], d = ei[EE + idx];
    float4 ex = *reinterpret_cast<const float4*>(ebuf + (size_t)idx * 4);
    float4 dn = *reinterpret_cast<const float4*>(den + (size_t)d * 4);
    int head = lane >> 4;
    float exs = (head == 0) ? ex.x : (head == 1) ? ex.y : (head == 2) ? ex.z : ex.w;
    float dns = (head == 0) ? dn.x : (head == 1) ? dn.y : (head == 2) ? dn.z : dn.w;
    float al = exs / dns;
    uint2 hr = *reinterpret_cast<const uint2*>(hw + (size_t)s * 256 + lane * 4);
    float2 f01 = __half22float2(*reinterpret_cast<__half2*>(&hr.x));
    float2 f23 = __half22float2(*reinterpret_cast<__half2*>(&hr.y));
    unsigned h2a = pack_h2(f01.x * al, f01.y * al);
    unsigned h2b = pack_h2(f23.x * al, f23.y * al);
    redh4(acc + (size_t)d * 256 + lane * 4, h2a, h2b);
}

// ---------------- LN(256) of (acc + alpha_self*hw + bias), ReLU, half out ---------------
__global__ void ln_relu_k(const __half* __restrict__ in, const __half* __restrict__ hw,
                          const float* __restrict__ asrc, const float* __restrict__ adst,
                          const float* __restrict__ den,
                          const float* __restrict__ bias,
                          const float* __restrict__ g, const float* __restrict__ b,
                          __half* __restrict__ out)
{
    int row = (blockIdx.x * blockDim.x + threadIdx.x) >> 5;
    int lane = threadIdx.x & 31;
    if (row >= NN) return;
    int h = lane >> 3;
    float es = leaky(asrc[row * 4 + h] + adst[row * 4 + h]);
    float al = expf(es) / den[row * 4 + h];

    const float4* bsp = reinterpret_cast<const float4*>(bias);
    uint4 au = *reinterpret_cast<const uint4*>(in + (size_t)row * 256 + lane * 8);
    float2 i01 = __half22float2(*reinterpret_cast<__half2*>(&au.x));
    float2 i23 = __half22float2(*reinterpret_cast<__half2*>(&au.y));
    float2 i45 = __half22float2(*reinterpret_cast<__half2*>(&au.z));
    float2 i67 = __half22float2(*reinterpret_cast<__half2*>(&au.w));
    uint4 hu = *reinterpret_cast<const uint4*>(hw + (size_t)row * 256 + lane * 8);
    float2 h01 = __half22float2(*reinterpret_cast<__half2*>(&hu.x));
    float2 h23 = __half22float2(*reinterpret_cast<__half2*>(&hu.y));
    float2 h45 = __half22float2(*reinterpret_cast<__half2*>(&hu.z));
    float2 h67 = __half22float2(*reinterpret_cast<__half2*>(&hu.w));
    float4 a0 = bsp[lane * 2], a1 = bsp[lane * 2 + 1];
    float4 v0, v1;
    v0.x = i01.x + al * h01.x + a0.x; v0.y = i01.y + al * h01.y + a0.y;
    v0.z = i23.x + al * h23.x + a0.z; v0.w = i23.y + al * h23.y + a0.w;
    v1.x = i45.x + al * h45.x + a1.x; v1.y = i45.y + al * h45.y + a1.y;
    v1.z = i67.x + al * h67.x + a1.z; v1.w = i67.y + al * h67.y + a1.w;
    float sum = v0.x + v0.y + v0.z + v0.w + v1.x + v1.y + v1.z + v1.w;
#pragma unroll
    for (int off = 16; off; off >>= 1) sum += __shfl_xor_sync(0xffffffffu, sum, off);
    float mean = sum * (1.f / 256.f);
    float c0x = v0.x - mean, c0y = v0.y - mean, c0z = v0.z - mean, c0w = v0.w - mean;
    float c1x = v1.x - mean, c1y = v1.y - mean, c1z = v1.z - mean, c1w = v1.w - mean;
    float sq = c0x * c0x + c0y * c0y + c0z * c0z + c0w * c0w
             + c1x * c1x + c1y * c1y + c1z * c1z + c1w * c1w;
#pragma unroll
    for (int off = 16; off; off >>= 1) sq += __shfl_xor_sync(0xffffffffu, sq, off);
    float r = rsqrtf(sq * (1.f / 256.f) + 1e-5f);
    const float4* gp = reinterpret_cast<const float4*>(g);
    const float4* bp = reinterpret_cast<const float4*>(b);
    float4 g0 = gp[lane * 2], g1 = gp[lane * 2 + 1];
    float4 b0 = bp[lane * 2], b1 = bp[lane * 2 + 1];
    uint4 u;
    u.x = pack_h2(fmaxf(c0x * r * g0.x + b0.x, 0.f), fmaxf(c0y * r * g0.y + b0.y, 0.f));
    u.y = pack_h2(fmaxf(c0z * r * g0.z + b0.z, 0.f), fmaxf(c0w * r * g0.w + b0.w, 0.f));
    u.z = pack_h2(fmaxf(c1x * r * g1.x + b1.x, 0.f), fmaxf(c1y * r * g1.y + b1.y, 0.f));
    u.w = pack_h2(fmaxf(c1z * r * g1.z + b1.z, 0.f), fmaxf(c1w * r * g1.w + b1.w, 0.f));
    *reinterpret_cast<uint4*>(out + (size_t)row * 256 + lane * 8) = u;
}

// ---------------- launcher ----------------
extern "C" void kernel_launch(void* const* d_in, const int* in_sizes, int n_in,
                              void* d_out, int out_size)
{
    const float* x       = (const float*)d_in[0];
    const int*   ei_bu   = (const int*)d_in[1];
    const int*   ei_td   = (const int*)d_in[2];
    const float* Wp      = (const float*)d_in[3];
    const float* bp      = (const float*)d_in[4];
    const float* W_bu    = (const float*)d_in[5];
    const float* asrc_bu = (const float*)d_in[6];
    const float* adst_bu = (const float*)d_in[7];
    const float* bias_bu = (const float*)d_in[8];
    const float* W_td    = (const float*)d_in[9];
    const float* asrc_td = (const float*)d_in[10];
    const float* adst_td = (const float*)d_in[11];
    const float* bias_td = (const float*)d_in[12];
    const float* Wf      = (const float*)d_in[13];
    const float* bf      = (const float*)d_in[14];
    const float* g_bu    = (const float*)d_in[15];
    const float* b_bu    = (const float*)d_in[16];
    const float* g_td    = (const float*)d_in[17];
    const float* b_td    = (const float*)d_in[18];
    const float* g_out   = (const float*)d_in[19];
    const float* b_out   = (const float*)d_in[20];
    float* out = (float*)d_out;

    __half *ph, *pxbu, *pxtd, *pwt;
    __half *phw[2], *pacc[2];
    float *pas[2], *pad[2], *pden[2], *pe[2];
    cudaGetSymbolAddress((void**)&ph,      g_h);
    cudaGetSymbolAddress((void**)&phw[0],  g_hw0);
    cudaGetSymbolAddress((void**)&phw[1],  g_hw1);
    cudaGetSymbolAddress((void**)&pacc[0], g_acc0);
    cudaGetSymbolAddress((void**)&pacc[1], g_acc1);
    cudaGetSymbolAddress((void**)&pxbu,    g_xbu);
    cudaGetSymbolAddress((void**)&pxtd,    g_xtd);
    cudaGetSymbolAddress((void**)&pas[0],  g_as0);
    cudaGetSymbolAddress((void**)&pas[1],  g_as1);
    cudaGetSymbolAddress((void**)&pad[0],  g_ad0);
    cudaGetSymbolAddress((void**)&pad[1],  g_ad1);
    cudaGetSymbolAddress((void**)&pden[0], g_den0);
    cudaGetSymbolAddress((void**)&pden[1], g_den1);
    cudaGetSymbolAddress((void**)&pe[0],   g_e0);
    cudaGetSymbolAddress((void**)&pe[1],   g_e1);
    cudaGetSymbolAddress((void**)&pwt,     g_wt);

    static cudaStream_t sc[2] = {nullptr, nullptr};
    static cudaEvent_t evFork = nullptr, evG[2] = {nullptr, nullptr}, evJ[2] = {nullptr, nullptr};
    if (sc[0] == nullptr) {
        cudaStreamCreateWithFlags(&sc[0], cudaStreamNonBlocking);
        cudaStreamCreateWithFlags(&sc[1], cudaStreamNonBlocking);
        cudaEventCreateWithFlags(&evFork, cudaEventDisableTiming);
        cudaEventCreateWithFlags(&evG[0], cudaEventDisableTiming);
        cudaEventCreateWithFlags(&evG[1], cudaEventDisableTiming);
        cudaEventCreateWithFlags(&evJ[0], cudaEventDisableTiming);
        cudaEventCreateWithFlags(&evJ[1], cudaEventDisableTiming);
    }

    const int mblocks = (NN + 127) / 128;               // 1563
    const int warpRowBlocks = (NN * 32) / 256;          // 25000
    const int edgeBlocks    = (EE + 255) / 256;         // 782
    const int scatBlocks    = (EE + 3) / 4;             // 50000

    round_w_k<<<256, 256>>>(Wp, W_bu, W_td, Wf, pwt);

    // h = half(relu(x @ Wp + bp))  (BN=256, single column block)
    tgemm16_cvt_k<<<mblocks, 512>>>(x, pwt, bp, ph, NN, 256, 256);

    cudaEventRecord(evFork, 0);
    cudaStreamWaitEvent(sc[0], evFork, 0);
    cudaStreamWaitEvent(sc[1], evFork, 0);
    cudaMemsetAsync(pacc[0], 0, (size_t)NN * 256 * sizeof(__half), sc[0]);
    cudaMemsetAsync(pacc[1], 0, (size_t)NN * 256 * sizeof(__half), sc[1]);

    const int*   eis[2]   = {ei_bu, ei_td};
    const float* asr[2]   = {asrc_bu, asrc_td};
    const float* ads[2]   = {adst_bu, adst_td};
    const float* bis[2]   = {bias_bu, bias_td};
    const float* gln[2]   = {g_bu, g_td};
    const float* bln[2]   = {b_bu, b_td};
    __half*      xdir[2]  = {pxbu, pxtd};

    for (int dir = 0; dir < 2; dir++) {
        tgemm16_att_k<<<mblocks, 512>>>(
            ph, pwt + 65536 + dir * 65536, phw[dir], NN, 256, 256,
            asr[dir], ads[dir], pas[dir], pad[dir], pden[dir]);
        cudaEventRecord(evG[dir], 0);
        cudaStreamWaitEvent(sc[dir], evG[dir], 0);
        cudaStream_t st = sc[dir];
        edge_expsum_k<<<edgeBlocks, 256, 0, st>>>(eis[dir], pas[dir], pad[dir], pe[dir], pden[dir]);
        edge_scatter_k<<<scatBlocks, 256, 0, st>>>(eis[dir], pe[dir], pden[dir], phw[dir], pacc[dir]);
        ln_relu_k<<<warpRowBlocks, 256, 0, st>>>(pacc[dir], phw[dir], pas[dir], pad[dir],
                                                 pden[dir],
                                                 bis[dir], gln[dir], bln[dir], xdir[dir]);
        cudaEventRecord(evJ[dir], st);
    }

    cudaStreamWaitEvent(0, evJ[0], 0);
    cudaStreamWaitEvent(0, evJ[1], 0);

    // out = L2norm(LN(concat(x_bu, x_td) @ Wf + bf))
    tgemm16_final_k<<<mblocks, 256>>>(pxbu, pxtd, 256, pwt + 196608, bf,
                                      g_out, b_out, out, NN, 512);
}

// round 17
// speedup vs baseline: 1.1010x; 1.1010x over previous
#include <cuda_runtime.h>
#include <cuda_fp16.h>
#include <cstdint>

#define NN 200000
#define EE 200000

// ---------------- scratch (static device globals; no runtime allocation) ----------------
__device__ __half   g_h   [(size_t)NN * 256];
__device__ __half   g_hw0 [(size_t)NN * 256];
__device__ __half   g_hw1 [(size_t)NN * 256];
__device__ __half   g_acc0[(size_t)NN * 256];
__device__ __half   g_acc1[(size_t)NN * 256];
__device__ __half   g_xbu [(size_t)NN * 256];
__device__ __half   g_xtd [(size_t)NN * 256];
__device__ float    g_as0 [NN * 4];
__device__ float    g_as1 [NN * 4];
__device__ float    g_ad0 [NN * 4];
__device__ float    g_ad1 [NN * 4];
__device__ float    g_den0[NN * 4];
__device__ float    g_den1[NN * 4];
__device__ float    g_e0  [(size_t)EE * 4];
__device__ float    g_e1  [(size_t)EE * 4];
__device__ __half   g_wt  [4 * 65536];   // half-rounded Wp | W_bu | W_td | Wf

// ---------------- helpers ----------------
__device__ __forceinline__ unsigned pack_h2(float a, float b) {
    __half2 h = __floats2half2_rn(a, b);
    return *reinterpret_cast<unsigned*>(&h);
}

__device__ __forceinline__ void mma16(float c[4], const unsigned a[4], const unsigned b[2]) {
    asm volatile(
        "mma.sync.aligned.m16n8k16.row.col.f32.f16.f16.f32 "
        "{%0,%1,%2,%3}, {%4,%5,%6,%7}, {%8,%9}, {%0,%1,%2,%3};\n"
        : "+f"(c[0]), "+f"(c[1]), "+f"(c[2]), "+f"(c[3])
        : "r"(a[0]), "r"(a[1]), "r"(a[2]), "r"(a[3]), "r"(b[0]), "r"(b[1]));
}

__device__ __forceinline__ void ldsm4(unsigned& r0, unsigned& r1, unsigned& r2, unsigned& r3,
                                      uint32_t addr) {
    asm volatile("ldmatrix.sync.aligned.m8n8.x4.shared.b16 {%0,%1,%2,%3}, [%4];\n"
                 : "=r"(r0), "=r"(r1), "=r"(r2), "=r"(r3) : "r"(addr));
}
__device__ __forceinline__ void ldsm4t(unsigned& r0, unsigned& r1, unsigned& r2, unsigned& r3,
                                       uint32_t addr) {
    asm volatile("ldmatrix.sync.aligned.m8n8.x4.trans.shared.b16 {%0,%1,%2,%3}, [%4];\n"
                 : "=r"(r0), "=r"(r1), "=r"(r2), "=r"(r3) : "r"(addr));
}

__device__ __forceinline__ void cp16(void* smem_dst, const void* gsrc, bool pred) {
    uint32_t s = (uint32_t)__cvta_generic_to_shared(smem_dst);
    int sz = pred ? 16 : 0;
    asm volatile("cp.async.cg.shared.global [%0], [%1], 16, %2;\n"
                 :: "r"(s), "l"(gsrc), "r"(sz));
}
__device__ __forceinline__ void cp_commit() { asm volatile("cp.async.commit_group;\n"); }
template<int N>
__device__ __forceinline__ void cp_wait() { asm volatile("cp.async.wait_group %0;\n" :: "n"(N)); }

// vector f16x2 reduction (sm_90+): adds 4 halves at [p]
__device__ __forceinline__ void redh4(__half* p, unsigned h2a, unsigned h2b) {
    asm volatile("red.global.add.noftz.v2.f16x2 [%0], {%1,%2};\n"
                 :: "l"(p), "r"(h2a), "r"(h2b) : "memory");
}

__device__ __forceinline__ void red4(float* p, float4 v) {
    asm volatile("red.global.add.v4.f32 [%0], {%1,%2,%3,%4};\n"
                 :: "l"(p), "f"(v.x), "f"(v.y), "f"(v.z), "f"(v.w) : "memory");
}

__device__ __forceinline__ float leaky(float v) { return v > 0.f ? v : 0.2f * v; }

// smem geometry (halves): As stride 24 (48B/row), Bs stride 136 (272B/row)
#define AS_STRIDE 24
#define BS_STRIDE 136
#define AS_STAGE_B (128u * AS_STRIDE * 2u)   // 6144
#define BS_STAGE_B (16u * BS_STRIDE * 2u)    // 4352

// fp16 inner compute: 4 ldsm + 2 ldsm.trans + 16 mma per k-tile (K=16)
__device__ __forceinline__ void compute16(uint32_t asBase, uint32_t bsBase, int s,
                                          float acc[4][4][4], int wm, int wn, int lane)
{
    int sel = lane >> 3, r = lane & 7;
    uint32_t arow = (uint32_t)(wm * 64 + (sel & 1) * 8 + r);
    uint32_t acol = (uint32_t)((sel >> 1) * 8);
    uint32_t abase = asBase + (uint32_t)s * AS_STAGE_B + arow * (AS_STRIDE * 2u) + acol * 2u;
    uint32_t kk = (uint32_t)((sel & 1) * 8 + r);
    unsigned a[4][4], b[4][2];
#pragma unroll
    for (int mt = 0; mt < 4; mt++)
        ldsm4(a[mt][0], a[mt][1], a[mt][2], a[mt][3],
              abase + (uint32_t)mt * 16u * (AS_STRIDE * 2u));
#pragma unroll
    for (int p = 0; p < 2; p++) {
        uint32_t ncol = (uint32_t)(wn * 32 + p * 16 + (sel >> 1) * 8);
        unsigned r0, r1, r2, r3;
        ldsm4t(r0, r1, r2, r3,
               bsBase + (uint32_t)s * BS_STAGE_B + kk * (BS_STRIDE * 2u) + ncol * 2u);
        b[p * 2][0] = r0;     b[p * 2][1] = r1;
        b[p * 2 + 1][0] = r2; b[p * 2 + 1][1] = r3;
    }
#pragma unroll
    for (int mt = 0; mt < 4; mt++)
#pragma unroll
        for (int nt = 0; nt < 4; nt++)
            mma16(acc[mt][nt], a[mt], b[nt]);
}

// ---------------- GEMM1: A fp32 (register-staged cvt), B half, out half, relu+bias -------
__global__ void __launch_bounds__(256) tgemm16_cvt_k(
    const float* __restrict__ A1,
    const __half* __restrict__ B, const float* __restrict__ bias,
    __half* __restrict__ C, int M, int K, int Nc)
{
    __shared__ __align__(16) __half As[2][128][AS_STRIDE];
    __shared__ __align__(16) __half Bs[2][16][BS_STRIDE];

    int tid = threadIdx.x;
    int lane = tid & 31, wid = tid >> 5;
    int g = lane >> 2, t = lane & 3;
    int wm = wid >> 2, wn = wid & 3;
    int rowBase = blockIdx.y * 128;
    int colBase = blockIdx.x * 128;
    uint32_t asBase = (uint32_t)__cvta_generic_to_shared(&As[0][0][0]);
    uint32_t bsBase = (uint32_t)__cvta_generic_to_shared(&Bs[0][0][0]);

    float acc[4][4][4];
#pragma unroll
    for (int i = 0; i < 4; i++)
#pragma unroll
        for (int j = 0; j < 4; j++)
#pragma unroll
            for (int r = 0; r < 4; r++) acc[i][j][r] = 0.f;

    int ar = tid >> 1, ac = (tid & 1) * 8;
    int br = tid >> 4, bc = (tid & 15) * 8;

    float4 pa0, pa1;
    const float4 z4 = make_float4(0.f, 0.f, 0.f, 0.f);

    auto aload = [&](int kt) {
        int rr = rowBase + ar;
        pa0 = (rr < M) ? *reinterpret_cast<const float4*>(A1 + (size_t)rr * K + kt + ac) : z4;
        pa1 = (rr < M) ? *reinterpret_cast<const float4*>(A1 + (size_t)rr * K + kt + ac + 4) : z4;
    };
    auto astore = [&](int sb) {
        uint4 u;
        u.x = pack_h2(pa0.x, pa0.y); u.y = pack_h2(pa0.z, pa0.w);
        u.z = pack_h2(pa1.x, pa1.y); u.w = pack_h2(pa1.z, pa1.w);
        *reinterpret_cast<uint4*>(&As[sb][ar][ac]) = u;
    };
    auto bload = [&](int kt, int sb) {
        cp16(&Bs[sb][br][bc], B + (size_t)(kt + br) * Nc + colBase + bc, true);
        cp_commit();
    };

    int ntiles = K / 16;
    aload(0); astore(0);
    bload(0, 0);
    for (int kt = 0; kt < ntiles; kt++) {
        int s = kt & 1;
        bool more = (kt + 1 < ntiles);
        if (more) { bload((kt + 1) * 16, s ^ 1); aload((kt + 1) * 16); }
        else cp_commit();
        cp_wait<1>();
        __syncthreads();
        compute16(asBase, bsBase, s, acc, wm, wn, lane);
        if (more) astore(s ^ 1);
        __syncthreads();
    }

#pragma unroll
    for (int nt = 0; nt < 4; nt++) {
        int col = colBase + wn * 32 + nt * 8 + 2 * t;
        float2 bb = *reinterpret_cast<const float2*>(bias + col);
#pragma unroll
        for (int mt = 0; mt < 4; mt++) {
            int row0 = rowBase + wm * 64 + mt * 16 + g;
            int row1 = row0 + 8;
            float v00 = fmaxf(acc[mt][nt][0] + bb.x, 0.f);
            float v01 = fmaxf(acc[mt][nt][1] + bb.y, 0.f);
            float v10 = fmaxf(acc[mt][nt][2] + bb.x, 0.f);
            float v11 = fmaxf(acc[mt][nt][3] + bb.y, 0.f);
            if (row0 < M) *reinterpret_cast<unsigned*>(C + (size_t)row0 * Nc + col) = pack_h2(v00, v01);
            if (row1 < M) *reinterpret_cast<unsigned*>(C + (size_t)row1 * Nc + col) = pack_h2(v10, v11);
        }
    }
}

// ---------------- GEMM2: 3-stage cp.async, fused attention-coeff + den epilogue ---------
__global__ void __launch_bounds__(256) tgemm16_att_k(
    const __half* __restrict__ A1,
    const __half* __restrict__ B,
    __half* __restrict__ C, int M, int K, int Nc,
    const float* __restrict__ asrc, const float* __restrict__ adst,
    float* __restrict__ osrc, float* __restrict__ odst, float* __restrict__ oden)
{
    __shared__ __align__(16) __half As[3][128][AS_STRIDE];
    __shared__ __align__(16) __half Bs[3][16][BS_STRIDE];
    __shared__ float attS[128][2];
    __shared__ float attD[128][2];

    int tid = threadIdx.x;
    int lane = tid & 31, wid = tid >> 5;
    int g = lane >> 2, t = lane & 3;
    int wm = wid >> 2, wn = wid & 3;
    int rowBase = blockIdx.y * 128;
    int colBase = blockIdx.x * 128;
    uint32_t asBase = (uint32_t)__cvta_generic_to_shared(&As[0][0][0]);
    uint32_t bsBase = (uint32_t)__cvta_generic_to_shared(&Bs[0][0][0]);

    if (tid < 128) {
        attS[tid][0] = 0.f; attS[tid][1] = 0.f;
        attD[tid][0] = 0.f; attD[tid][1] = 0.f;
    }

    float acc[4][4][4];
#pragma unroll
    for (int i = 0; i < 4; i++)
#pragma unroll
        for (int j = 0; j < 4; j++)
#pragma unroll
            for (int r = 0; r < 4; r++) acc[i][j][r] = 0.f;

    int ar = tid >> 1, ac = (tid & 1) * 8;
    int br = tid >> 4, bc = (tid & 15) * 8;

    auto loadtile = [&](int kt, int sb) {
        int rr = rowBase + ar;
        cp16(&As[sb][ar][ac], A1 + (size_t)rr * K + kt + ac, rr < M);
        cp16(&Bs[sb][br][bc], B + (size_t)(kt + br) * Nc + colBase + bc, true);
        cp_commit();
    };

    int ntiles = K / 16;           // 16
    loadtile(0, 0);
    loadtile(16, 1);
    for (int kt = 0; kt < ntiles; kt++) {
        int s = kt % 3;
        cp_wait<1>();
        __syncthreads();
        if (kt + 2 < ntiles) loadtile((kt + 2) * 16, (kt + 2) % 3);
        else cp_commit();
        compute16(asBase, bsBase, s, acc, wm, wn, lane);
    }
    __syncthreads();

    float as_c[4][2], ad_c[4][2];
#pragma unroll
    for (int nt = 0; nt < 4; nt++) {
        int colG = colBase + wn * 32 + nt * 8 + 2 * t;
        float2 a2 = *reinterpret_cast<const float2*>(asrc + colG);
        float2 d2 = *reinterpret_cast<const float2*>(adst + colG);
        as_c[nt][0] = a2.x; as_c[nt][1] = a2.y;
        ad_c[nt][0] = d2.x; ad_c[nt][1] = d2.y;
    }
    int hl = wn >> 1;

#pragma unroll
    for (int mt = 0; mt < 4; mt++) {
        float s0 = 0.f, d0 = 0.f, s1 = 0.f, d1 = 0.f;
#pragma unroll
        for (int nt = 0; nt < 4; nt++) {
            s0 += acc[mt][nt][0] * as_c[nt][0] + acc[mt][nt][1] * as_c[nt][1];
            d0 += acc[mt][nt][0] * ad_c[nt][0] + acc[mt][nt][1] * ad_c[nt][1];
            s1 += acc[mt][nt][2] * as_c[nt][0] + acc[mt][nt][3] * as_c[nt][1];
            d1 += acc[mt][nt][2] * ad_c[nt][0] + acc[mt][nt][3] * ad_c[nt][1];
        }
#pragma unroll
        for (int off = 1; off <= 2; off <<= 1) {
            s0 += __shfl_xor_sync(0xffffffffu, s0, off);
            d0 += __shfl_xor_sync(0xffffffffu, d0, off);
            s1 += __shfl_xor_sync(0xffffffffu, s1, off);
            d1 += __shfl_xor_sync(0xffffffffu, d1, off);
        }
        if (t == 0) {
            int lr = wm * 64 + mt * 16 + g;
            atomicAdd(&attS[lr][hl], s0);
            atomicAdd(&attD[lr][hl], d0);
            atomicAdd(&attS[lr + 8][hl], s1);
            atomicAdd(&attD[lr + 8][hl], d1);
        }
#pragma unroll
        for (int nt = 0; nt < 4; nt++) {
            int col = colBase + wn * 32 + nt * 8 + 2 * t;
            int row0 = rowBase + wm * 64 + mt * 16 + g;
            int row1 = row0 + 8;
            if (row0 < M) *reinterpret_cast<unsigned*>(C + (size_t)row0 * Nc + col)
                = pack_h2(acc[mt][nt][0], acc[mt][nt][1]);
            if (row1 < M) *reinterpret_cast<unsigned*>(C + (size_t)row1 * Nc + col)
                = pack_h2(acc[mt][nt][2], acc[mt][nt][3]);
        }
    }
    __syncthreads();
    if (tid < 256) {
        int lr = tid >> 1, h = tid & 1;
        int grow = rowBase + lr;
        if (grow < M) {
            float sv = attS[lr][h], dv = attD[lr][h];
            size_t o = (size_t)grow * 4 + blockIdx.x * 2 + h;
            osrc[o] = sv;
            odst[o] = dv;
            oden[o] = expf(leaky(sv + dv));   // self-loop softmax seed
        }
    }
}

// ---------------- final GEMM: 3-stage, concat(A1,A2)@Wf + bf, fused LN(128) + L2 --------
__global__ void __launch_bounds__(256) tgemm16_final_k(
    const __half* __restrict__ A1, const __half* __restrict__ A2, int K1,
    const __half* __restrict__ B, const float* __restrict__ bias,
    const float* __restrict__ gw, const float* __restrict__ bw,
    float* __restrict__ C, int M, int K)
{
    const int Nc = 128;
    __shared__ __align__(16) __half As[3][128][AS_STRIDE];
    __shared__ __align__(16) __half Bs[3][16][BS_STRIDE];
    __shared__ float redS[128], redQ[128], redN[128];

    int tid = threadIdx.x;
    int lane = tid & 31, wid = tid >> 5;
    int g = lane >> 2, t = lane & 3;
    int wm = wid >> 2, wn = wid & 3;
    int rowBase = blockIdx.x * 128;
    uint32_t asBase = (uint32_t)__cvta_generic_to_shared(&As[0][0][0]);
    uint32_t bsBase = (uint32_t)__cvta_generic_to_shared(&Bs[0][0][0]);

    if (tid < 128) { redS[tid] = 0.f; redQ[tid] = 0.f; redN[tid] = 0.f; }

    float acc[4][4][4];
#pragma unroll
    for (int i = 0; i < 4; i++)
#pragma unroll
        for (int j = 0; j < 4; j++)
#pragma unroll
            for (int r = 0; r < 4; r++) acc[i][j][r] = 0.f;

    int ar = tid >> 1, ac = (tid & 1) * 8;
    int br = tid >> 4, bc = (tid & 15) * 8;

    auto loadtile = [&](int kt, int sb) {
        const __half* Ap; int kk, stride;
        if (kt < K1) { Ap = A1; kk = kt;      stride = K1;     }
        else         { Ap = A2; kk = kt - K1; stride = K - K1; }
        int rr = rowBase + ar;
        cp16(&As[sb][ar][ac], Ap + (size_t)rr * stride + kk + ac, rr < M);
        cp16(&Bs[sb][br][bc], B + (size_t)(kt + br) * Nc + bc, true);
        cp_commit();
    };

    int ntiles = K / 16;           // 32
    loadtile(0, 0);
    loadtile(16, 1);
    for (int kt = 0; kt < ntiles; kt++) {
        int s = kt % 3;
        cp_wait<1>();
        __syncthreads();
        if (kt + 2 < ntiles) loadtile((kt + 2) * 16, (kt + 2) % 3);
        else cp_commit();
        compute16(asBase, bsBase, s, acc, wm, wn, lane);
    }
    __syncthreads();

#pragma unroll
    for (int nt = 0; nt < 4; nt++) {
        int col = wn * 32 + nt * 8 + 2 * t;
        float2 bb = *reinterpret_cast<const float2*>(bias + col);
#pragma unroll
        for (int mt = 0; mt < 4; mt++) {
            acc[mt][nt][0] += bb.x; acc[mt][nt][1] += bb.y;
            acc[mt][nt][2] += bb.x; acc[mt][nt][3] += bb.y;
        }
    }
#pragma unroll
    for (int mt = 0; mt < 4; mt++) {
        float s0 = 0.f, q0 = 0.f, s1 = 0.f, q1 = 0.f;
#pragma unroll
        for (int nt = 0; nt < 4; nt++) {
            s0 += acc[mt][nt][0] + acc[mt][nt][1];
            q0 += acc[mt][nt][0] * acc[mt][nt][0] + acc[mt][nt][1] * acc[mt][nt][1];
            s1 += acc[mt][nt][2] + acc[mt][nt][3];
            q1 += acc[mt][nt][2] * acc[mt][nt][2] + acc[mt][nt][3] * acc[mt][nt][3];
        }
#pragma unroll
        for (int off = 1; off <= 2; off <<= 1) {
            s0 += __shfl_xor_sync(0xffffffffu, s0, off);
            q0 += __shfl_xor_sync(0xffffffffu, q0, off);
            s1 += __shfl_xor_sync(0xffffffffu, s1, off);
            q1 += __shfl_xor_sync(0xffffffffu, q1, off);
        }
        if (t == 0) {
            int lr = wm * 64 + mt * 16 + g;
            atomicAdd(&redS[lr], s0); atomicAdd(&redQ[lr], q0);
            atomicAdd(&redS[lr + 8], s1); atomicAdd(&redQ[lr + 8], q1);
        }
    }
    __syncthreads();
#pragma unroll
    for (int mt = 0; mt < 4; mt++) {
        int lr0 = wm * 64 + mt * 16 + g, lr1 = lr0 + 8;
        float m0 = redS[lr0] * (1.f / 128.f), m1 = redS[lr1] * (1.f / 128.f);
        float var0 = redQ[lr0] * (1.f / 128.f) - m0 * m0;
        float var1 = redQ[lr1] * (1.f / 128.f) - m1 * m1;
        float r0 = rsqrtf(var0 + 1e-5f), r1 = rsqrtf(var1 + 1e-5f);
        float n0 = 0.f, n1 = 0.f;
#pragma unroll
        for (int nt = 0; nt < 4; nt++) {
            int col = wn * 32 + nt * 8 + 2 * t;
            float2 gg = *reinterpret_cast<const float2*>(gw + col);
            float2 b2 = *reinterpret_cast<const float2*>(bw + col);
            float y00 = (acc[mt][nt][0] - m0) * r0 * gg.x + b2.x;
            float y01 = (acc[mt][nt][1] - m0) * r0 * gg.y + b2.y;
            float y10 = (acc[mt][nt][2] - m1) * r1 * gg.x + b2.x;
            float y11 = (acc[mt][nt][3] - m1) * r1 * gg.y + b2.y;
            acc[mt][nt][0] = y00; acc[mt][nt][1] = y01;
            acc[mt][nt][2] = y10; acc[mt][nt][3] = y11;
            n0 += y00 * y00 + y01 * y01;
            n1 += y10 * y10 + y11 * y11;
        }
#pragma unroll
        for (int off = 1; off <= 2; off <<= 1) {
            n0 += __shfl_xor_sync(0xffffffffu, n0, off);
            n1 += __shfl_xor_sync(0xffffffffu, n1, off);
        }
        if (t == 0) { atomicAdd(&redN[lr0], n0); atomicAdd(&redN[lr1], n1); }
    }
    __syncthreads();
#pragma unroll
    for (int mt = 0; mt < 4; mt++) {
        int lr0 = wm * 64 + mt * 16 + g, lr1 = lr0 + 8;
        float inv0 = 1.f / fmaxf(sqrtf(redN[lr0]), 1e-12f);
        float inv1 = 1.f / fmaxf(sqrtf(redN[lr1]), 1e-12f);
        int row0 = rowBase + lr0, row1 = rowBase + lr1;
#pragma unroll
        for (int nt = 0; nt < 4; nt++) {
            int col = wn * 32 + nt * 8 + 2 * t;
            if (row0 < M) *reinterpret_cast<float2*>(C + (size_t)row0 * 128 + col)
                = make_float2(acc[mt][nt][0] * inv0, acc[mt][nt][1] * inv0);
            if (row1 < M) *reinterpret_cast<float2*>(C + (size_t)row1 * 128 + col)
                = make_float2(acc[mt][nt][2] * inv1, acc[mt][nt][3] * inv1);
        }
    }
}

// ---------------- convert weights once into g_wt (half) ----------------
__global__ void round_w_k(const float* __restrict__ wp, const float* __restrict__ w0,
                          const float* __restrict__ w1, const float* __restrict__ w2,
                          __half* __restrict__ out)
{
    int i = blockIdx.x * 256 + threadIdx.x;
    out[i]           = __float2half_rn(wp[i]);
    out[65536 + i]   = __float2half_rn(w0[i]);
    out[131072 + i]  = __float2half_rn(w1[i]);
    out[196608 + i]  = __float2half_rn(w2[i]);
}

// ---------------- fused edge pass: exp(logit) + segment-sum into den --------------------
__global__ void edge_expsum_k(const int* __restrict__ ei,
                              const float* __restrict__ asrc, const float* __restrict__ adst,
                              float* __restrict__ ebuf, float* __restrict__ den)
{
    int i = blockIdx.x * blockDim.x + threadIdx.x;
    if (i >= EE) return;
    int s = ei[i], d = ei[EE + i];
    float4 as = *reinterpret_cast<const float4*>(asrc + (size_t)s * 4);
    float4 ad = *reinterpret_cast<const float4*>(adst + (size_t)d * 4);
    float4 o;
    o.x = expf(leaky(as.x + ad.x));
    o.y = expf(leaky(as.y + ad.y));
    o.z = expf(leaky(as.z + ad.z));
    o.w = expf(leaky(as.w + ad.w));
    *reinterpret_cast<float4*>(ebuf + (size_t)i * 4) = o;
    red4(den + (size_t)d * 4, o);
}

// ---------------- edge scatter: 32 lanes/edge, uint4 hw loads, 2x redh4 ----------------
__global__ void __launch_bounds__(256) edge_scatter_k(const int* __restrict__ ei,
        const float* __restrict__ ebuf, const float* __restrict__ den,
        const __half* __restrict__ hw, __half* __restrict__ acc)
{
    int idx = blockIdx.x * 8 + (threadIdx.x >> 5);
    int lane = threadIdx.x & 31;
    if (idx >= EE) return;
    int s = ei[idx], d = ei[EE + idx];
    float4 ex = *reinterpret_cast<const float4*>(ebuf + (size_t)idx * 4);
    float4 dn = *reinterpret_cast<const float4*>(den + (size_t)d * 4);
    int head = lane >> 3;   // 8 channels per lane -> head = (lane*8)/64
    float exs = (head == 0) ? ex.x : (head == 1) ? ex.y : (head == 2) ? ex.z : ex.w;
    float dns = (head == 0) ? dn.x : (head == 1) ? dn.y : (head == 2) ? dn.z : dn.w;
    float al = exs / dns;
    uint4 hr = *reinterpret_cast<const uint4*>(hw + (size_t)s * 256 + lane * 8);
    float2 f01 = __half22float2(*reinterpret_cast<__half2*>(&hr.x));
    float2 f23 = __half22float2(*reinterpret_cast<__half2*>(&hr.y));
    float2 f45 = __half22float2(*reinterpret_cast<__half2*>(&hr.z));
    float2 f67 = __half22float2(*reinterpret_cast<__half2*>(&hr.w));
    unsigned a0 = pack_h2(f01.x * al, f01.y * al);
    unsigned a1 = pack_h2(f23.x * al, f23.y * al);
    unsigned a2 = pack_h2(f45.x * al, f45.y * al);
    unsigned a3 = pack_h2(f67.x * al, f67.y * al);
    __half* base = acc + (size_t)d * 256 + lane * 8;
    redh4(base, a0, a1);
    redh4(base + 4, a2, a3);
}

// ---------------- LN(256) of (acc + alpha_self*hw + bias), ReLU, half out ---------------
__global__ void ln_relu_k(const __half* __restrict__ in, const __half* __restrict__ hw,
                          const float* __restrict__ asrc, const float* __restrict__ adst,
                          const float* __restrict__ den,
                          const float* __restrict__ bias,
                          const float* __restrict__ g, const float* __restrict__ b,
                          __half* __restrict__ out)
{
    int row = (blockIdx.x * blockDim.x + threadIdx.x) >> 5;
    int lane = threadIdx.x & 31;
    if (row >= NN) return;
    int h = lane >> 3;
    float es = leaky(asrc[row * 4 + h] + adst[row * 4 + h]);
    float al = expf(es) / den[row * 4 + h];

    const float4* bsp = reinterpret_cast<const float4*>(bias);
    uint4 au = *reinterpret_cast<const uint4*>(in + (size_t)row * 256 + lane * 8);
    float2 i01 = __half22float2(*reinterpret_cast<__half2*>(&au.x));
    float2 i23 = __half22float2(*reinterpret_cast<__half2*>(&au.y));
    float2 i45 = __half22float2(*reinterpret_cast<__half2*>(&au.z));
    float2 i67 = __half22float2(*reinterpret_cast<__half2*>(&au.w));
    uint4 hu = *reinterpret_cast<const uint4*>(hw + (size_t)row * 256 + lane * 8);
    float2 h01 = __half22float2(*reinterpret_cast<__half2*>(&hu.x));
    float2 h23 = __half22float2(*reinterpret_cast<__half2*>(&hu.y));
    float2 h45 = __half22float2(*reinterpret_cast<__half2*>(&hu.z));
    float2 h67 = __half22float2(*reinterpret_cast<__half2*>(&hu.w));
    float4 a0 = bsp[lane * 2], a1 = bsp[lane * 2 + 1];
    float4 v0, v1;
    v0.x = i01.x + al * h01.x + a0.x; v0.y = i01.y + al * h01.y + a0.y;
    v0.z = i23.x + al * h23.x + a0.z; v0.w = i23.y + al * h23.y + a0.w;
    v1.x = i45.x + al * h45.x + a1.x; v1.y = i45.y + al * h45.y + a1.y;
    v1.z = i67.x + al * h67.x + a1.z; v1.w = i67.y + al * h67.y + a1.w;
    float sum = v0.x + v0.y + v0.z + v0.w + v1.x + v1.y + v1.z + v1.w;
#pragma unroll
    for (int off = 16; off; off >>= 1) sum += __shfl_xor_sync(0xffffffffu, sum, off);
    float mean = sum * (1.f / 256.f);
    float c0x = v0.x - mean, c0y = v0.y - mean, c0z = v0.z - mean, c0w = v0.w - mean;
    float c1x = v1.x - mean, c1y = v1.y - mean, c1z = v1.z - mean, c1w = v1.w - mean;
    float sq = c0x * c0x + c0y * c0y + c0z * c0z + c0w * c0w
             + c1x * c1x + c1y * c1y + c1z * c1z + c1w * c1w;
#pragma unroll
    for (int off = 16; off; off >>= 1) sq += __shfl_xor_sync(0xffffffffu, sq, off);
    float r = rsqrtf(sq * (1.f / 256.f) + 1e-5f);
    const float4* gp = reinterpret_cast<const float4*>(g);
    const float4* bp = reinterpret_cast<const float4*>(b);
    float4 g0 = gp[lane * 2], g1 = gp[lane * 2 + 1];
    float4 b0 = bp[lane * 2], b1 = bp[lane * 2 + 1];
    uint4 u;
    u.x = pack_h2(fmaxf(c0x * r * g0.x + b0.x, 0.f), fmaxf(c0y * r * g0.y + b0.y, 0.f));
    u.y = pack_h2(fmaxf(c0z * r * g0.z + b0.z, 0.f), fmaxf(c0w * r * g0.w + b0.w, 0.f));
    u.z = pack_h2(fmaxf(c1x * r * g1.x + b1.x, 0.f), fmaxf(c1y * r * g1.y + b1.y, 0.f));
    u.w = pack_h2(fmaxf(c1z * r * g1.z + b1.z, 0.f), fmaxf(c1w * r * g1.w + b1.w, 0.f));
    *reinterpret_cast<uint4*>(out + (size_t)row * 256 + lane * 8) = u;
}

// ---------------- launcher ----------------
extern "C" void kernel_launch(void* const* d_in, const int* in_sizes, int n_in,
                              void* d_out, int out_size)
{
    const float* x       = (const float*)d_in[0];
    const int*   ei_bu   = (const int*)d_in[1];
    const int*   ei_td   = (const int*)d_in[2];
    const float* Wp      = (const float*)d_in[3];
    const float* bp      = (const float*)d_in[4];
    const float* W_bu    = (const float*)d_in[5];
    const float* asrc_bu = (const float*)d_in[6];
    const float* adst_bu = (const float*)d_in[7];
    const float* bias_bu = (const float*)d_in[8];
    const float* W_td    = (const float*)d_in[9];
    const float* asrc_td = (const float*)d_in[10];
    const float* adst_td = (const float*)d_in[11];
    const float* bias_td = (const float*)d_in[12];
    const float* Wf      = (const float*)d_in[13];
    const float* bf      = (const float*)d_in[14];
    const float* g_bu    = (const float*)d_in[15];
    const float* b_bu    = (const float*)d_in[16];
    const float* g_td    = (const float*)d_in[17];
    const float* b_td    = (const float*)d_in[18];
    const float* g_out   = (const float*)d_in[19];
    const float* b_out   = (const float*)d_in[20];
    float* out = (float*)d_out;

    __half *ph, *pxbu, *pxtd, *pwt;
    __half *phw[2], *pacc[2];
    float *pas[2], *pad[2], *pden[2], *pe[2];
    cudaGetSymbolAddress((void**)&ph,      g_h);
    cudaGetSymbolAddress((void**)&phw[0],  g_hw0);
    cudaGetSymbolAddress((void**)&phw[1],  g_hw1);
    cudaGetSymbolAddress((void**)&pacc[0], g_acc0);
    cudaGetSymbolAddress((void**)&pacc[1], g_acc1);
    cudaGetSymbolAddress((void**)&pxbu,    g_xbu);
    cudaGetSymbolAddress((void**)&pxtd,    g_xtd);
    cudaGetSymbolAddress((void**)&pas[0],  g_as0);
    cudaGetSymbolAddress((void**)&pas[1],  g_as1);
    cudaGetSymbolAddress((void**)&pad[0],  g_ad0);
    cudaGetSymbolAddress((void**)&pad[1],  g_ad1);
    cudaGetSymbolAddress((void**)&pden[0], g_den0);
    cudaGetSymbolAddress((void**)&pden[1], g_den1);
    cudaGetSymbolAddress((void**)&pe[0],   g_e0);
    cudaGetSymbolAddress((void**)&pe[1],   g_e1);
    cudaGetSymbolAddress((void**)&pwt,     g_wt);

    static cudaStream_t sc[2] = {nullptr, nullptr};
    static cudaEvent_t evFork = nullptr, evG[2] = {nullptr, nullptr}, evJ[2] = {nullptr, nullptr};
    if (sc[0] == nullptr) {
        cudaStreamCreateWithFlags(&sc[0], cudaStreamNonBlocking);
        cudaStreamCreateWithFlags(&sc[1], cudaStreamNonBlocking);
        cudaEventCreateWithFlags(&evFork, cudaEventDisableTiming);
        cudaEventCreateWithFlags(&evG[0], cudaEventDisableTiming);
        cudaEventCreateWithFlags(&evG[1], cudaEventDisableTiming);
        cudaEventCreateWithFlags(&evJ[0], cudaEventDisableTiming);
        cudaEventCreateWithFlags(&evJ[1], cudaEventDisableTiming);
    }

    const int mblocks = (NN + 127) / 128;               // 1563
    const dim3 gemmGrid256(2, mblocks);
    const int warpRowBlocks = (NN * 32) / 256;          // 25000
    const int edgeBlocks    = (EE + 255) / 256;         // 782
    const int scatBlocks    = (EE + 7) / 8;             // 25000

    round_w_k<<<256, 256>>>(Wp, W_bu, W_td, Wf, pwt);

    // h = half(relu(x @ Wp + bp))
    tgemm16_cvt_k<<<gemmGrid256, 256>>>(x, pwt, bp, ph, NN, 256, 256);

    cudaEventRecord(evFork, 0);
    cudaStreamWaitEvent(sc[0], evFork, 0);
    cudaStreamWaitEvent(sc[1], evFork, 0);
    cudaMemsetAsync(pacc[0], 0, (size_t)NN * 256 * sizeof(__half), sc[0]);
    cudaMemsetAsync(pacc[1], 0, (size_t)NN * 256 * sizeof(__half), sc[1]);

    const int*   eis[2]   = {ei_bu, ei_td};
    const float* asr[2]   = {asrc_bu, asrc_td};
    const float* ads[2]   = {adst_bu, adst_td};
    const float* bis[2]   = {bias_bu, bias_td};
    const float* gln[2]   = {g_bu, g_td};
    const float* bln[2]   = {b_bu, b_td};
    __half*      xdir[2]  = {pxbu, pxtd};

    for (int dir = 0; dir < 2; dir++) {
        tgemm16_att_k<<<gemmGrid256, 256>>>(
            ph, pwt + 65536 + dir * 65536, phw[dir], NN, 256, 256,
            asr[dir], ads[dir], pas[dir], pad[dir], pden[dir]);
        cudaEventRecord(evG[dir], 0);
        cudaStreamWaitEvent(sc[dir], evG[dir], 0);
        cudaStream_t st = sc[dir];
        edge_expsum_k<<<edgeBlocks, 256, 0, st>>>(eis[dir], pas[dir], pad[dir], pe[dir], pden[dir]);
        edge_scatter_k<<<scatBlocks, 256, 0, st>>>(eis[dir], pe[dir], pden[dir], phw[dir], pacc[dir]);
        ln_relu_k<<<warpRowBlocks, 256, 0, st>>>(pacc[dir], phw[dir], pas[dir], pad[dir],
                                                 pden[dir],
                                                 bis[dir], gln[dir], bln[dir], xdir[dir]);
        cudaEventRecord(evJ[dir], st);
    }

    cudaStreamWaitEvent(0, evJ[0], 0);
    cudaStreamWaitEvent(0, evJ[1], 0);

    // out = L2norm(LN(concat(x_bu, x_td) @ Wf + bf))
    tgemm16_final_k<<<mblocks, 256>>>(pxbu, pxtd, 256, pwt + 196608, bf,
                                      g_out, b_out, out, NN, 512);
}